// round 7
// baseline (speedup 1.0000x reference)
#include <cuda_runtime.h>
#include <math.h>
#include <stdint.h>

// Problem constants
#define BB 2048
#define TT 500
#define LL 128
#define DD 64
#define UU 128
#define RB 16              // batch rows per block
#define NBLK (BB / RB)     // 128 blocks
#define NTHR 512

typedef unsigned long long u64;

// ---------------------------------------------------------------------------
// Packed f32x2 FMA (FFMA2) — only reachable via PTX fma.rn.f32x2
// ---------------------------------------------------------------------------
__device__ __forceinline__ void fma2(u64 &c, u64 a, u64 b) {
    asm("fma.rn.f32x2 %0, %1, %2, %0;" : "+l"(c) : "l"(a), "l"(b));
}
__device__ __forceinline__ float f2sum(u64 v) {
    return __uint_as_float((unsigned)v) + __uint_as_float((unsigned)(v >> 32));
}
__device__ __forceinline__ ulonglong2 ld2s(const char *p) {            // LDS.128
    return *reinterpret_cast<const ulonglong2 *>(p);
}
__device__ __forceinline__ ulonglong2 ld2g(const char *p) {            // LDG.128
    return *reinterpret_cast<const ulonglong2 *>(p);
}

__device__ __forceinline__ float sig_f(float x) {          // fast sigmoid
    return __fdividef(1.0f, 1.0f + __expf(-x));
}
__device__ __forceinline__ float tanh_f(float x) {         // fast tanh
    return 2.0f * __fdividef(1.0f, 1.0f + __expf(-2.0f * x)) - 1.0f;
}

// Named barrier (register id + count)
#define BARX(id, cnt) \
    asm volatile("bar.sync %0, %1;" :: "r"(id), "r"(cnt) : "memory")

// ---------------------------------------------------------------------------
// Streamed weights, pre-packed into [k4][col] float4 layout (prep kernel)
// ---------------------------------------------------------------------------
__device__ float4 g_wihq[16 * 384];   // w_ih[:, 0:64]  : [k4<16][j<384]
__device__ float4 g_w1q [32 * 128];   // w1             : [k4<32][q<128]
__device__ float4 g_w2q [32 * 64];    // w2             : [q4<32][d<64]

__global__ void prep_kernel(const float *__restrict__ w_ih,
                            const float *__restrict__ w1,
                            const float *__restrict__ w2) {
    int idx = blockIdx.x * blockDim.x + threadIdx.x;
    int stride = gridDim.x * blockDim.x;
    for (int i = idx; i < 16 * 384; i += stride) {
        int k4 = i / 384, j = i % 384;
        const float *s = w_ih + j * 65 + 4 * k4;       // row length 65 (last = dt)
        g_wihq[i] = make_float4(s[0], s[1], s[2], s[3]);
    }
    for (int i = idx; i < 32 * 128; i += stride) {
        int k4 = i / 128, q = i % 128;
        const float *s = w1 + q * 128 + 4 * k4;
        g_w1q[i] = make_float4(s[0], s[1], s[2], s[3]);
    }
    for (int i = idx; i < 32 * 64; i += stride) {
        int q4 = i / 64, d = i % 64;
        const float *s = w2 + d * 128 + 4 * q4;
        g_w2q[i] = make_float4(s[0], s[1], s[2], s[3]);
    }
}

// ---------------------------------------------------------------------------
// Shared memory layout (bytes)
// ---------------------------------------------------------------------------
#define SM_WHH    0
#define SM_WHH_SZ (32 * 384 * 16)            // 196608 : whh4[k4][j] float4
#define SM_H_SZ   (16 * 132 * 4)             // 8448  : h[16][132]
#define SM_H0     (SM_WHH + SM_WHH_SZ)
#define SM_H1     (SM_H0 + SM_H_SZ)          // double buffer
#define SM_U      (SM_H1 + SM_H_SZ)
#define SM_U_SZ   (16 * 132 * 4)             // 8448
#define SM_P      (SM_U + SM_U_SZ)
#define SM_P_SZ   (16 * 68 * 4)              // 4352  : p[16][68]
#define SM_DT     (SM_P + SM_P_SZ)
#define SM_DT_SZ  (512 * 4)
#define SM_TOTAL  (SM_DT + SM_DT_SZ)         // 228352 <= 232448

__global__ void __launch_bounds__(NTHR, 1)
rnn_kernel(const float *__restrict__ fp,     // first_point [1,B,L]
           const float *__restrict__ ts,     // [T]
           const float *__restrict__ w_hh,   // [384,128]
           const float *__restrict__ w_ih,   // [384,65]
           const float *__restrict__ b_ih,   // [384]
           const float *__restrict__ b_hh,   // [384]
           const float *__restrict__ b1,     // [128]
           const float *__restrict__ b2,     // [64]
           float *__restrict__ out_z,        // [B,T,L]
           float *__restrict__ out_p)        // [B,T,D]
{
    extern __shared__ char sm[];
    float  *h0_s = (float *)(sm + SM_H0);
    float  *h1_s = (float *)(sm + SM_H1);
    float  *u_s  = (float *)(sm + SM_U);
    float  *p_s  = (float *)(sm + SM_P);
    float  *dt_s = (float *)(sm + SM_DT);
    float4 *whh4 = (float4 *)(sm + SM_WHH);

    const int tid  = threadIdx.x;
    const int lane = tid & 31;
    const int warp = tid >> 5;
    const int row0 = blockIdx.x * RB;

    // ---- named-barrier ids: two independent 8-row half-pipelines
    const int halfid = warp >> 3;                // 0 | 1
    const int barA   = 1 + halfid * 2;           // A -> D       (256 thr)
    const int barB   = 2 + halfid * 2;           // E -> next A  (256 thr)
    const int barQ   = 5 + (warp >> 2);          // D -> E       (128 thr)

    // ---- one-time: w_hh -> smem, whh4[k4*384 + j] = w_hh[j][4k4..4k4+3]
    for (int i = tid; i < 32 * 384; i += NTHR) {
        int k4 = i / 384, j = i % 384;
        whh4[i] = *reinterpret_cast<const float4 *>(w_hh + j * 128 + 4 * k4);
    }
    for (int i = tid; i < TT; i += NTHR)
        dt_s[i] = (i == 0) ? 0.0f : (ts[i] - ts[i - 1]);

    // ---- phase A mapping: (jA in 0..127, ksA in 0..1 lane-bit4, r0A row half)
    const int jA  = ((warp & 7) << 4) | (lane & 15);
    const int ksA = lane >> 4;
    const int r0A = (warp >> 3) * 8;
    const float cR  = b_ih[jA] + b_hh[jA];
    const float cZ  = b_ih[jA + 128] + b_hh[jA + 128];
    const float biN = b_ih[jA + 256];
    const float bhN = b_hh[jA + 256];
    const float wtR = w_ih[jA * 65 + 64];
    const float wtZ = w_ih[(jA + 128) * 65 + 64];
    const float wtN = w_ih[(jA + 256) * 65 + 64];

    // ---- phase D mapping: (q4 in 0..31, rqD rows, ksD lane bits 3..4)
    const int q4  = ((warp & 3) << 3) | (lane & 7);
    const int ksD = lane >> 3;                 // 0..3
    const int rqD = warp >> 2;                 // 0..3  (quarter-aligned rows)
    const float4 b1v = *reinterpret_cast<const float4 *>(b1 + 4 * q4);

    // ---- phase E mapping: (d4 in 0..15, rqE rows, ksE lane bits 2..4)
    const int d4  = ((warp & 3) << 2) | (lane & 3);
    const int ksE = lane >> 2;                 // 0..7
    const int rqE = warp >> 2;                 // 0..3
    const float4 b2v = *reinterpret_cast<const float4 *>(b2 + 4 * d4);

    // ---- coalesced sol_z writer mapping (warp w -> row w: half-aligned)
    const int rW = tid >> 5, cW = (tid & 31) * 4;

    // ---- load h0 into buffer 0
    {
        float4 v = *reinterpret_cast<const float4 *>(fp + (size_t)(row0 + rW) * LL + cW);
        *reinterpret_cast<float4 *>(&h0_s[rW * 132 + cW]) = v;
    }
    __syncthreads();

    for (int t = 0; t < TT; ++t) {
        float *h_cur  = (t & 1) ? h1_s : h0_s;   // state after step t
        float *h_prev = (t & 1) ? h0_s : h1_s;   // state after step t-1

        if (t > 0) {
            // ===== Phase A: GRU gates, tile 8 rows x 3 gates, ksplit 2 =====
            u64 aR[8], aZ[8], aN1[8], aN2[8];   // N1 = i_n (from p), N2 = h_n (from h)
#pragma unroll
            for (int i = 0; i < 8; ++i) { aR[i] = 0; aZ[i] = 0; aN1[i] = 0; aN2[i] = 0; }

            // gh = h_prev @ w_hh^T : K-half interleaved k4 = 2*kk + ksA
            {
                const char *wp = (const char *)(whh4 + ksA * 384 + jA);
                const char *hp = (const char *)h_prev + (size_t)(r0A * 132 + 4 * ksA) * 4;
#pragma unroll 4
                for (int kk = 0; kk < 16; ++kk) {
                    ulonglong2 wr = ld2s(wp);
                    ulonglong2 wz = ld2s(wp + 128 * 16);
                    ulonglong2 wn = ld2s(wp + 256 * 16);
#pragma unroll
                    for (int i = 0; i < 8; ++i) {
                        ulonglong2 h = ld2s(hp + i * 528);
                        fma2(aR[i],  wr.x, h.x); fma2(aR[i],  wr.y, h.y);
                        fma2(aZ[i],  wz.x, h.x); fma2(aZ[i],  wz.y, h.y);
                        fma2(aN2[i], wn.x, h.x); fma2(aN2[i], wn.y, h.y);
                    }
                    wp += 2 * 384 * 16;
                    hp += 32;
                }
            }
            // gi = p @ w_ih[:, :64]^T : k4 = 2*kk + ksA (8 iters)
            {
                const char *wp = (const char *)(g_wihq + ksA * 384 + jA);
                const char *pp = (const char *)p_s + (size_t)(r0A * 68 + 4 * ksA) * 4;
#pragma unroll 2
                for (int kk = 0; kk < 8; ++kk) {
                    ulonglong2 wr = ld2g(wp);
                    ulonglong2 wz = ld2g(wp + 128 * 16);
                    ulonglong2 wn = ld2g(wp + 256 * 16);
#pragma unroll
                    for (int i = 0; i < 8; ++i) {
                        ulonglong2 p = ld2s(pp + i * 272);
                        fma2(aR[i],  wr.x, p.x); fma2(aR[i],  wr.y, p.y);
                        fma2(aZ[i],  wz.x, p.x); fma2(aZ[i],  wz.y, p.y);
                        fma2(aN1[i], wn.x, p.x); fma2(aN1[i], wn.y, p.y);
                    }
                    wp += 2 * 384 * 16;
                    pp += 32;
                }
            }
            // reduce ks pairs + gates; write h_cur (other buffer -> no barrier)
            const float dtv = dt_s[t];
#pragma unroll
            for (int i = 0; i < 8; ++i) {
                float sR = f2sum(aR[i]);  sR += __shfl_xor_sync(0xffffffffu, sR, 16);
                float sZ = f2sum(aZ[i]);  sZ += __shfl_xor_sync(0xffffffffu, sZ, 16);
                float sI = f2sum(aN1[i]); sI += __shfl_xor_sync(0xffffffffu, sI, 16);
                float sH = f2sum(aN2[i]); sH += __shfl_xor_sync(0xffffffffu, sH, 16);
                float rg = sig_f(sR + cR + dtv * wtR);
                float zg = sig_f(sZ + cZ + dtv * wtZ);
                float ng = tanh_f(sI + biN + dtv * wtN + rg * (sH + bhN));
                float hold = h_prev[(r0A + i) * 132 + jA];
                if (ksA == 0)
                    h_cur[(r0A + i) * 132 + jA] = (1.0f - zg) * ng + zg * hold;
            }
            BARX(barA, 256);   // h_cur rows of this half visible to the half
        }

        // ===== sol_z[t] writer (coalesced 512B/warp) =====
        {
            float4 v = *reinterpret_cast<const float4 *>(&h_cur[rW * 132 + cW]);
            *reinterpret_cast<float4 *>(
                &out_z[((size_t)(row0 + rW) * TT + t) * LL + cW]) = v;
        }

        // ===== Phase D: u = tanh(h @ w1^T + b1), tile 4x4, ksplit 4 =====
        {
            u64 c[16];
#pragma unroll
            for (int i = 0; i < 16; ++i) c[i] = 0;
            const char *wp = (const char *)(g_w1q + ksD * 128 + 4 * q4);
            const char *hp = (const char *)h_cur + (size_t)(rqD * 4 * 132 + 4 * ksD) * 4;
#pragma unroll 2
            for (int kk = 0; kk < 8; ++kk) {
                ulonglong2 w0 = ld2g(wp);
                ulonglong2 w1r = ld2g(wp + 16);
                ulonglong2 w2r = ld2g(wp + 32);
                ulonglong2 w3r = ld2g(wp + 48);
#pragma unroll
                for (int i = 0; i < 4; ++i) {
                    ulonglong2 h = ld2s(hp + i * 528);
                    fma2(c[i * 4 + 0], w0.x,  h.x); fma2(c[i * 4 + 0], w0.y,  h.y);
                    fma2(c[i * 4 + 1], w1r.x, h.x); fma2(c[i * 4 + 1], w1r.y, h.y);
                    fma2(c[i * 4 + 2], w2r.x, h.x); fma2(c[i * 4 + 2], w2r.y, h.y);
                    fma2(c[i * 4 + 3], w3r.x, h.x); fma2(c[i * 4 + 3], w3r.y, h.y);
                }
                wp += 4 * 128 * 16;
                hp += 64;
            }
#pragma unroll
            for (int i = 0; i < 4; ++i) {
                float s0 = f2sum(c[i * 4 + 0]);
                float s1 = f2sum(c[i * 4 + 1]);
                float s2 = f2sum(c[i * 4 + 2]);
                float s3 = f2sum(c[i * 4 + 3]);
                s0 += __shfl_xor_sync(0xffffffffu, s0, 8);
                s1 += __shfl_xor_sync(0xffffffffu, s1, 8);
                s2 += __shfl_xor_sync(0xffffffffu, s2, 8);
                s3 += __shfl_xor_sync(0xffffffffu, s3, 8);
                s0 += __shfl_xor_sync(0xffffffffu, s0, 16);
                s1 += __shfl_xor_sync(0xffffffffu, s1, 16);
                s2 += __shfl_xor_sync(0xffffffffu, s2, 16);
                s3 += __shfl_xor_sync(0xffffffffu, s3, 16);
                if (ksD == 0) {
                    float4 uv = make_float4(tanh_f(s0 + b1v.x), tanh_f(s1 + b1v.y),
                                            tanh_f(s2 + b1v.z), tanh_f(s3 + b1v.w));
                    *reinterpret_cast<float4 *>(&u_s[(rqD * 4 + i) * 132 + 4 * q4]) = uv;
                }
            }
        }
        BARX(barQ, 128);       // u rows of this quarter ready

        // ===== Phase E: p = u @ w2^T + b2, tile 4x4, ksplit 8 =====
        {
            u64 c[16];
#pragma unroll
            for (int i = 0; i < 16; ++i) c[i] = 0;
            const char *wp = (const char *)(g_w2q + ksE * 64 + 4 * d4);
            const char *up = (const char *)u_s + (size_t)(rqE * 4 * 132 + 4 * ksE) * 4;
#pragma unroll
            for (int kk = 0; kk < 4; ++kk) {
                ulonglong2 w0 = ld2g(wp);
                ulonglong2 w1r = ld2g(wp + 16);
                ulonglong2 w2r = ld2g(wp + 32);
                ulonglong2 w3r = ld2g(wp + 48);
#pragma unroll
                for (int i = 0; i < 4; ++i) {
                    ulonglong2 u = ld2s(up + i * 528);
                    fma2(c[i * 4 + 0], w0.x,  u.x); fma2(c[i * 4 + 0], w0.y,  u.y);
                    fma2(c[i * 4 + 1], w1r.x, u.x); fma2(c[i * 4 + 1], w1r.y, u.y);
                    fma2(c[i * 4 + 2], w2r.x, u.x); fma2(c[i * 4 + 2], w2r.y, u.y);
                    fma2(c[i * 4 + 3], w3r.x, u.x); fma2(c[i * 4 + 3], w3r.y, u.y);
                }
                wp += 8 * 64 * 16;
                up += 128;
            }
#pragma unroll
            for (int i = 0; i < 4; ++i) {
                float s0 = f2sum(c[i * 4 + 0]);
                float s1 = f2sum(c[i * 4 + 1]);
                float s2 = f2sum(c[i * 4 + 2]);
                float s3 = f2sum(c[i * 4 + 3]);
                s0 += __shfl_xor_sync(0xffffffffu, s0, 4);
                s1 += __shfl_xor_sync(0xffffffffu, s1, 4);
                s2 += __shfl_xor_sync(0xffffffffu, s2, 4);
                s3 += __shfl_xor_sync(0xffffffffu, s3, 4);
                s0 += __shfl_xor_sync(0xffffffffu, s0, 8);
                s1 += __shfl_xor_sync(0xffffffffu, s1, 8);
                s2 += __shfl_xor_sync(0xffffffffu, s2, 8);
                s3 += __shfl_xor_sync(0xffffffffu, s3, 8);
                s0 += __shfl_xor_sync(0xffffffffu, s0, 16);
                s1 += __shfl_xor_sync(0xffffffffu, s1, 16);
                s2 += __shfl_xor_sync(0xffffffffu, s2, 16);
                s3 += __shfl_xor_sync(0xffffffffu, s3, 16);
                if (ksE == 0) {
                    float4 pv = make_float4(s0 + b2v.x, s1 + b2v.y,
                                            s2 + b2v.z, s3 + b2v.w);
                    int r = rqE * 4 + i;
                    *reinterpret_cast<float4 *>(&p_s[r * 68 + 4 * d4]) = pv;
                    *reinterpret_cast<float4 *>(
                        &out_p[((size_t)(row0 + r) * TT + t) * DD + 4 * d4]) = pv;
                }
            }
        }
        BARX(barB, 256);       // p rows of this half ready for next step's A
    }
}

// ---------------------------------------------------------------------------
// Launch
// ---------------------------------------------------------------------------
extern "C" void kernel_launch(void *const *d_in, const int *in_sizes, int n_in,
                              void *d_out, int out_size) {
    const float *fp   = (const float *)d_in[0];
    const float *ts   = (const float *)d_in[1];
    const float *w_ih = (const float *)d_in[2];
    const float *w_hh = (const float *)d_in[3];
    const float *b_ih = (const float *)d_in[4];
    const float *b_hh = (const float *)d_in[5];
    const float *w1   = (const float *)d_in[6];
    const float *b1   = (const float *)d_in[7];
    const float *w2   = (const float *)d_in[8];
    const float *b2   = (const float *)d_in[9];

    float *out_z = (float *)d_out;                       // sol_z  [1,B,T,L]
    float *out_p = out_z + (size_t)BB * TT * LL;         // pred_x [1,B,T,D]

    prep_kernel<<<64, 256>>>(w_ih, w1, w2);

    cudaFuncSetAttribute(rnn_kernel, cudaFuncAttributeMaxDynamicSharedMemorySize,
                         SM_TOTAL);
    rnn_kernel<<<NBLK, NTHR, SM_TOTAL>>>(fp, ts, w_hh, w_ih, b_ih, b_hh, b1, b2,
                                         out_z, out_p);
}

// round 14
// speedup vs baseline: 1.2482x; 1.2482x over previous
#include <cuda_runtime.h>
#include <cuda_bf16.h>
#include <math.h>
#include <stdint.h>

// Problem constants
#define BB 2048
#define TT 500
#define LL 128
#define DD 64
#define UU 128
#define RB 16              // batch rows per block
#define NBLK (BB / RB)     // 128 blocks
#define NTHR 512

// tcgen05 only exists in the arch-specific (sm_103a) device pass.
#if defined(__CUDA_ARCH_FEAT_SM103_ALL)
#define USE_TC 1
#else
#define USE_TC 0
#endif

typedef unsigned long long u64;

// ---------------------------------------------------------------------------
// f32x2 FMA helpers
// ---------------------------------------------------------------------------
__device__ __forceinline__ void fma2(u64 &c, u64 a, u64 b) {
    asm("fma.rn.f32x2 %0, %1, %2, %0;" : "+l"(c) : "l"(a), "l"(b));
}
__device__ __forceinline__ float f2sum(u64 v) {
    return __uint_as_float((unsigned)v) + __uint_as_float((unsigned)(v >> 32));
}
__device__ __forceinline__ ulonglong2 ld2s(const char *p) {            // LDS.128
    return *reinterpret_cast<const ulonglong2 *>(p);
}
__device__ __forceinline__ ulonglong2 ld2g(const char *p) {            // LDG.128
    return *reinterpret_cast<const ulonglong2 *>(p);
}
__device__ __forceinline__ float sig_f(float x) {
    return __fdividef(1.0f, 1.0f + __expf(-x));
}
__device__ __forceinline__ float tanh_f(float x) {
    return 2.0f * __fdividef(1.0f, 1.0f + __expf(-2.0f * x)) - 1.0f;
}

__device__ __forceinline__ uint32_t smem_u32(const void *p) {
    uint32_t a;
    asm("{ .reg .u64 t; cvta.to.shared.u64 t, %1; cvt.u32.u64 %0, t; }"
        : "=r"(a) : "l"(p));
    return a;
}

#if USE_TC
// ---------------------------------------------------------------------------
// tcgen05 / mbarrier PTX helpers (arch-specific pass only)
// ---------------------------------------------------------------------------
#define TCALLOC(sa, n)                                                        \
    asm volatile("tcgen05.alloc.cta_group::1.sync.aligned.shared::cta.b32 [%0], %1;" \
                 :: "r"(sa), "r"(n) : "memory")
#define TCDEALLOC(t, n)                                                       \
    asm volatile("tcgen05.dealloc.cta_group::1.sync.aligned.b32 %0, %1;"      \
                 :: "r"(t), "r"(n))
#define TCRELINQ()                                                            \
    asm volatile("tcgen05.relinquish_alloc_permit.cta_group::1.sync.aligned;")
#define TCCOMMIT(m)                                                           \
    asm volatile("tcgen05.commit.cta_group::1.mbarrier::arrive::one.shared::cluster.b64 [%0];" \
                 :: "r"(m) : "memory")
#define TCFENCE_B() asm volatile("tcgen05.fence::before_thread_sync;" ::: "memory")
#define TCFENCE_A() asm volatile("tcgen05.fence::after_thread_sync;" ::: "memory")
#define TCWAIT_LD() asm volatile("tcgen05.wait::ld.sync.aligned;" ::: "memory")
#define FENCE_ASYNC() asm volatile("fence.proxy.async.shared::cta;" ::: "memory")
#define MBINIT(m, c)                                                          \
    asm volatile("mbarrier.init.shared.b64 [%0], %1;" :: "r"(m), "r"(c) : "memory")

#define MBWAIT(mbar_smem_addr, phase_parity) do {                             \
    uint32_t _mbar = (uint32_t)(mbar_smem_addr);                              \
    uint32_t _parity = (uint32_t)(phase_parity);                              \
    uint32_t _done;                                                           \
    asm volatile(                                                             \
        "{\n\t.reg .pred p;\n\t"                                              \
        "mbarrier.try_wait.parity.acquire.cta.shared::cta.b64 p, [%1], %2;\n\t" \
        "selp.b32 %0, 1, 0, p;\n\t}"                                          \
        : "=r"(_done) : "r"(_mbar), "r"(_parity) : "memory");                 \
    if (!_done) {                                                             \
        asm volatile(                                                         \
            "{\n\t.reg .pred P1;\n\t"                                         \
            "WAIT_LOOP_%=:\n\t"                                               \
            "mbarrier.try_wait.parity.acquire.cta.shared::cta.b64 P1, [%0], %1, 0x989680;\n\t" \
            "@P1 bra.uni WAIT_DONE_%=;\n\t"                                   \
            "bra.uni WAIT_LOOP_%=;\n\t"                                       \
            "WAIT_DONE_%=:\n\t}"                                              \
            :: "r"(_mbar), "r"(_parity) : "memory");                          \
    }                                                                         \
} while (0)

__device__ __forceinline__ void ldtm4(uint32_t *r, uint32_t ta) {
    asm volatile("tcgen05.ld.sync.aligned.32x32b.x4.b32 {%0,%1,%2,%3}, [%4];"
                 : "=r"(r[0]), "=r"(r[1]), "=r"(r[2]), "=r"(r[3]) : "r"(ta));
}

// idesc: dtype F32, atype BF16, btype BF16, N=16, M=128, K-major both
#define MMA_IDESC 0x8040490u

__device__ __forceinline__ void mma_ss(uint32_t d, uint64_t a, uint64_t b,
                                       uint32_t en) {
    asm volatile(
        "{\n\t.reg .pred p;\n\t"
        "setp.ne.u32 p, %4, 0;\n\t"
        "tcgen05.mma.cta_group::1.kind::f16 [%0], %1, %2, %3, {%5,%5,%5,%5}, p;\n\t}"
        :: "r"(d), "l"(a), "l"(b), "r"(MMA_IDESC), "r"(en), "r"(0u)
        : "memory");
}

// 64-bit SMEM descriptor (SW128, LBO=1, SBO=64)
#define DESC_BASE ((2ULL << 61) | (1ULL << 46) | (64ULL << 32) | (1ULL << 16))
__device__ __forceinline__ uint64_t mk_desc(uint32_t addr) {
    return DESC_BASE | ((uint64_t)(addr >> 4) & 0x3FFF);
}
#endif  // USE_TC

// Blocked-atom SW128 byte offsets (atom = 8 rows x 64 bf16 = 1024 B)
// A tile: 128 rows x 128 K (16 atom-rows, 2 atom-cols; col stride = 16 atoms)
__device__ __forceinline__ uint32_t a_off(int jj, int k) {
    uint32_t b = (uint32_t)((jj >> 3) + (k >> 6) * 16) * 1024u
               + (uint32_t)(jj & 7) * 128u + (uint32_t)(k & 63) * 2u;
    return b ^ ((b >> 3) & 0x70);
}
// B tile: 16 rows x 128 K (2 atom-rows, 2 atom-cols; col stride = 2 atoms)
__device__ __forceinline__ uint32_t b_off(int r, int k) {
    uint32_t b = (uint32_t)((r >> 3) + (k >> 6) * 2) * 1024u
               + (uint32_t)(r & 7) * 128u + (uint32_t)(k & 63) * 2u;
    return b ^ ((b >> 3) & 0x70);
}

// ---------------------------------------------------------------------------
// Streamed weights (prep kernel pre-pack)
// ---------------------------------------------------------------------------
__device__ float4 g_wihq[16 * 384];   // w_ih[:, 0:64]  : [k4<16][j<384]
__device__ float4 g_w1q [32 * 128];   // w1             : [k4<32][q<128]
__device__ float4 g_w2q [32 * 64];    // w2             : [q4<32][d<64]

__global__ void prep_kernel(const float *__restrict__ w_ih,
                            const float *__restrict__ w1,
                            const float *__restrict__ w2) {
    int idx = blockIdx.x * blockDim.x + threadIdx.x;
    int stride = gridDim.x * blockDim.x;
    for (int i = idx; i < 16 * 384; i += stride) {
        int k4 = i / 384, j = i % 384;
        const float *s = w_ih + j * 65 + 4 * k4;
        g_wihq[i] = make_float4(s[0], s[1], s[2], s[3]);
    }
    for (int i = idx; i < 32 * 128; i += stride) {
        int k4 = i / 128, q = i % 128;
        const float *s = w1 + q * 128 + 4 * k4;
        g_w1q[i] = make_float4(s[0], s[1], s[2], s[3]);
    }
    for (int i = idx; i < 32 * 64; i += stride) {
        int q4 = i / 64, d = i % 64;
        const float *s = w2 + d * 128 + 4 * q4;
        g_w2q[i] = make_float4(s[0], s[1], s[2], s[3]);
    }
}

// ---------------------------------------------------------------------------
// Shared memory layout (bytes) — identical footprint for BOTH paths.
// Region [0,196608): tensor path = w_hh bf16 hi/lo; fallback = w_hh fp32 quads
// Region [196608,204800): tensor path = h bf16 hi/lo B operand; fallback unused
// ---------------------------------------------------------------------------
#define SM_W0    0
#define SM_WHI   0                    // (tc) 3 gate tiles x 32768 bf16 hi
#define SM_WLO   98304                // (tc) bf16 lo
#define SM_HHI   196608               // (tc) h hi bf16 (4096)
#define SM_HLO   200704               // (tc) h lo bf16 (4096)
#define SM_H     204800               // h fp32 [16][132]  (8448)
#define SM_U     213248               // u fp32 [16][132]  (8448)
#define SM_P     221696               // p fp32 [16][68]   (4352)
#define SM_DT    226048               // dt [512]          (2048)
#define SM_MISC  228096               // [0]=tmem ptr, [8]=mbar
#define SM_TOTAL 228128               // <= 232448

__global__ void __launch_bounds__(NTHR, 1)
rnn_kernel(const float *__restrict__ fp,     // first_point [1,B,L]
           const float *__restrict__ ts,     // [T]
           const float *__restrict__ w_hh,   // [384,128]
           const float *__restrict__ w_ih,   // [384,65]
           const float *__restrict__ b_ih,   // [384]
           const float *__restrict__ b_hh,   // [384]
           const float *__restrict__ b1,     // [128]
           const float *__restrict__ b2,     // [64]
           float *__restrict__ out_z,        // [B,T,L]
           float *__restrict__ out_p)        // [B,T,D]
{
    extern __shared__ char sm[];
    float *h_s  = (float *)(sm + SM_H);
    float *u_s  = (float *)(sm + SM_U);
    float *p_s  = (float *)(sm + SM_P);
    float *dt_s = (float *)(sm + SM_DT);

    const int tid  = threadIdx.x;
    const int lane = tid & 31;
    const int warp = tid >> 5;
    const int row0 = blockIdx.x * RB;

#if USE_TC
    const uint32_t misc_sa = smem_u32(sm + SM_MISC);
    const uint32_t mbar_sa = misc_sa + 8;
    if (warp == 0) TCALLOC(misc_sa, 64);
    else if (warp == 1) TCRELINQ();
    if (tid == 0)  MBINIT(mbar_sa, 1);

    // one-time: w_hh -> smem bf16 hi/lo in blocked-atom SW128 layout
    for (int i = tid; i < 384 * 128; i += NTHR) {
        int j = i >> 7, k = i & 127;
        float v = w_hh[j * 128 + k];
        __nv_bfloat16 hi = __float2bfloat16(v);
        float lo = v - __bfloat162float(hi);
        int g = j >> 7, jj = j & 127;
        uint32_t off = (uint32_t)g * 32768u + a_off(jj, k);
        *(__nv_bfloat16 *)(sm + SM_WHI + off) = hi;
        *(__nv_bfloat16 *)(sm + SM_WLO + off) = __float2bfloat16(lo);
    }
#else
    // one-time: w_hh -> smem fp32, whh4[k4*384 + j] = w_hh[j][4k4..4k4+3]
    float4 *whh4 = (float4 *)(sm + SM_W0);
    for (int i = tid; i < 32 * 384; i += NTHR) {
        int k4 = i / 384, j = i % 384;
        whh4[i] = *reinterpret_cast<const float4 *>(w_hh + j * 128 + 4 * k4);
    }
#endif
    for (int i = tid; i < TT; i += NTHR)
        dt_s[i] = (i == 0) ? 0.0f : (ts[i] - ts[i - 1]);

#if USE_TC
    // gates mapping (tc): thread -> (jA = TMEM lane, 4 rows rq*4..)
    const int jA = ((warp & 3) << 5) | lane;
    const int rq = warp >> 2;                   // 0..3
    const float cR  = b_ih[jA] + b_hh[jA];
    const float cZ  = b_ih[jA + 128] + b_hh[jA + 128];
    const float biN = b_ih[jA + 256];
    const float bhN = b_hh[jA + 256];
    const float wtR = w_ih[jA * 65 + 64];
    const float wtZ = w_ih[(jA + 128) * 65 + 64];
    const float wtN = w_ih[(jA + 256) * 65 + 64];
#else
    // gates mapping (fallback, R6): (jF 0..127, ksA lane bit4, 8-row half)
    const int jF  = ((warp & 7) << 4) | (lane & 15);
    const int ksA = lane >> 4;
    const int r0A = (warp >> 3) * 8;
    const float cRf  = b_ih[jF] + b_hh[jF];
    const float cZf  = b_ih[jF + 128] + b_hh[jF + 128];
    const float biNf = b_ih[jF + 256];
    const float bhNf = b_hh[jF + 256];
    const float wtRf = w_ih[jF * 65 + 64];
    const float wtZf = w_ih[(jF + 128) * 65 + 64];
    const float wtNf = w_ih[(jF + 256) * 65 + 64];
#endif

    // phase D mapping: (q4 in 0..31, rqD rows, ksD lane bits 3..4)
    const int q4  = ((warp & 3) << 3) | (lane & 7);
    const int ksD = lane >> 3;                 // 0..3
    const int rqD = warp >> 2;                 // 0..3
    const float4 b1v = *reinterpret_cast<const float4 *>(b1 + 4 * q4);

    // phase E mapping: (d4 in 0..15, rqE rows, ksE lane bits 2..4)
    const int d4  = ((warp & 3) << 2) | (lane & 3);
    const int ksE = lane >> 2;                 // 0..7
    const int rqE = warp >> 2;                 // 0..3
    const float4 b2v = *reinterpret_cast<const float4 *>(b2 + 4 * d4);

    // coalesced sol_z writer mapping
    const int rW = tid >> 5, cW = (tid & 31) * 4;

    // ---- load h0
    {
        float4 v = *reinterpret_cast<const float4 *>(fp + (size_t)(row0 + rW) * LL + cW);
        *reinterpret_cast<float4 *>(&h_s[rW * 132 + cW]) = v;
#if USE_TC
        float hv[4] = {v.x, v.y, v.z, v.w};
#pragma unroll
        for (int c = 0; c < 4; ++c) {
            __nv_bfloat16 hi = __float2bfloat16(hv[c]);
            float lo = hv[c] - __bfloat162float(hi);
            uint32_t off = b_off(rW, cW + c);
            *(__nv_bfloat16 *)(sm + SM_HHI + off) = hi;
            *(__nv_bfloat16 *)(sm + SM_HLO + off) = __float2bfloat16(lo);
        }
#endif
    }
#if USE_TC
    FENCE_ASYNC();
#endif
    __syncthreads();

#if USE_TC
    const uint32_t tmem_base = *(volatile uint32_t *)(sm + SM_MISC);
#endif

    for (int t = 0; t < TT; ++t) {
        if (t > 0) {
#if USE_TC
            // ===== issue gh MMAs: D[g] = w_hi*h_hi + w_hi*h_lo + w_lo*h_hi
            if (tid == 0) {
                uint64_t bHi = mk_desc(smem_u32(sm + SM_HHI));
                uint64_t bLo = mk_desc(smem_u32(sm + SM_HLO));
#pragma unroll
                for (int g = 0; g < 3; ++g) {
                    uint32_t dcol = tmem_base + g * 16;
                    uint64_t aHi = mk_desc(smem_u32(sm + SM_WHI + g * 32768));
                    uint64_t aLo = mk_desc(smem_u32(sm + SM_WLO + g * 32768));
#pragma unroll
                    for (int s = 0; s < 8; ++s) {
                        uint64_t ao = (uint64_t)((s & 3) * 2 + (s >> 2) * 1024);
                        uint64_t bo = (uint64_t)((s & 3) * 2 + (s >> 2) * 128);
                        mma_ss(dcol, aHi + ao, bHi + bo, (s == 0) ? 0u : 1u);
                    }
#pragma unroll
                    for (int s = 0; s < 8; ++s) {
                        uint64_t ao = (uint64_t)((s & 3) * 2 + (s >> 2) * 1024);
                        uint64_t bo = (uint64_t)((s & 3) * 2 + (s >> 2) * 128);
                        mma_ss(dcol, aHi + ao, bLo + bo, 1u);
                    }
#pragma unroll
                    for (int s = 0; s < 8; ++s) {
                        uint64_t ao = (uint64_t)((s & 3) * 2 + (s >> 2) * 1024);
                        uint64_t bo = (uint64_t)((s & 3) * 2 + (s >> 2) * 128);
                        mma_ss(dcol, aLo + ao, bHi + bo, 1u);
                    }
                }
                TCCOMMIT(mbar_sa);
            }

            // ===== gi = p @ w_ih[:, :64]^T in fp32 (overlaps MMA) ============
            u64 cRa[4], cZa[4], cNa[4];
#pragma unroll
            for (int i = 0; i < 4; ++i) { cRa[i] = 0; cZa[i] = 0; cNa[i] = 0; }
            {
                const char *wp = (const char *)(g_wihq + jA);
                const char *pp = (const char *)p_s + (size_t)(rq * 4) * 272;
#pragma unroll 4
                for (int k4 = 0; k4 < 16; ++k4) {
                    ulonglong2 wr = ld2g(wp);
                    ulonglong2 wz = ld2g(wp + 128 * 16);
                    ulonglong2 wn = ld2g(wp + 256 * 16);
#pragma unroll
                    for (int i = 0; i < 4; ++i) {
                        ulonglong2 p = ld2s(pp + i * 272);
                        fma2(cRa[i], wr.x, p.x); fma2(cRa[i], wr.y, p.y);
                        fma2(cZa[i], wz.x, p.x); fma2(cZa[i], wz.y, p.y);
                        fma2(cNa[i], wn.x, p.x); fma2(cNa[i], wn.y, p.y);
                    }
                    wp += 384 * 16;
                    pp += 16;
                }
            }

            // ===== wait MMA, read gh from TMEM, compute gates ================
            MBWAIT(mbar_sa, (uint32_t)((t - 1) & 1));
            TCFENCE_A();
            uint32_t gr[4], gz[4], gn[4];
            ldtm4(gr, tmem_base + 0 * 16 + 4 * rq);
            ldtm4(gz, tmem_base + 1 * 16 + 4 * rq);
            ldtm4(gn, tmem_base + 2 * 16 + 4 * rq);
            TCWAIT_LD();
            TCFENCE_B();

            const float dtv = dt_s[t];
#pragma unroll
            for (int i = 0; i < 4; ++i) {
                int r = 4 * rq + i;
                float rg = sig_f(f2sum(cRa[i]) + cR + dtv * wtR +
                                 __uint_as_float(gr[i]));
                float zg = sig_f(f2sum(cZa[i]) + cZ + dtv * wtZ +
                                 __uint_as_float(gz[i]));
                float ng = tanh_f(f2sum(cNa[i]) + biN + dtv * wtN +
                                  rg * (__uint_as_float(gn[i]) + bhN));
                float hold = h_s[r * 132 + jA];
                float hn = (1.0f - zg) * ng + zg * hold;
                h_s[r * 132 + jA] = hn;                 // same-thread rd/wr: safe
                __nv_bfloat16 hi = __float2bfloat16(hn);
                float lo = hn - __bfloat162float(hi);
                uint32_t off = b_off(r, jA);
                *(__nv_bfloat16 *)(sm + SM_HHI + off) = hi;
                *(__nv_bfloat16 *)(sm + SM_HLO + off) = __float2bfloat16(lo);
            }
            FENCE_ASYNC();
            __syncthreads();   // h_t (fp32 + bf16 split) visible block-wide
#else
            // ===== fallback (R6): fp32 gates, tile 8 rows x 3 gates, ksplit 2
            u64 aR[8], aZ[8], aN1[8], aN2[8];
#pragma unroll
            for (int i = 0; i < 8; ++i) { aR[i] = 0; aZ[i] = 0; aN1[i] = 0; aN2[i] = 0; }
            {
                const char *wp = (const char *)(whh4 + ksA * 384 + jF);
                const char *hp = (const char *)h_s + (size_t)(r0A * 132 + 4 * ksA) * 4;
#pragma unroll 4
                for (int kk = 0; kk < 16; ++kk) {
                    ulonglong2 wr = ld2s(wp);
                    ulonglong2 wz = ld2s(wp + 128 * 16);
                    ulonglong2 wn = ld2s(wp + 256 * 16);
#pragma unroll
                    for (int i = 0; i < 8; ++i) {
                        ulonglong2 h = ld2s(hp + i * 528);
                        fma2(aR[i],  wr.x, h.x); fma2(aR[i],  wr.y, h.y);
                        fma2(aZ[i],  wz.x, h.x); fma2(aZ[i],  wz.y, h.y);
                        fma2(aN2[i], wn.x, h.x); fma2(aN2[i], wn.y, h.y);
                    }
                    wp += 2 * 384 * 16;
                    hp += 32;
                }
            }
            {
                const char *wp = (const char *)(g_wihq + ksA * 384 + jF);
                const char *pp = (const char *)p_s + (size_t)(r0A * 68 + 4 * ksA) * 4;
#pragma unroll 2
                for (int kk = 0; kk < 8; ++kk) {
                    ulonglong2 wr = ld2g(wp);
                    ulonglong2 wz = ld2g(wp + 128 * 16);
                    ulonglong2 wn = ld2g(wp + 256 * 16);
#pragma unroll
                    for (int i = 0; i < 8; ++i) {
                        ulonglong2 p = ld2s(pp + i * 272);
                        fma2(aR[i],  wr.x, p.x); fma2(aR[i],  wr.y, p.y);
                        fma2(aZ[i],  wz.x, p.x); fma2(aZ[i],  wz.y, p.y);
                        fma2(aN1[i], wn.x, p.x); fma2(aN1[i], wn.y, p.y);
                    }
                    wp += 2 * 384 * 16;
                    pp += 32;
                }
            }
            const float dtv = dt_s[t];
            float hn[8];
#pragma unroll
            for (int i = 0; i < 8; ++i) {
                float sR = f2sum(aR[i]);  sR += __shfl_xor_sync(0xffffffffu, sR, 16);
                float sZ = f2sum(aZ[i]);  sZ += __shfl_xor_sync(0xffffffffu, sZ, 16);
                float sI = f2sum(aN1[i]); sI += __shfl_xor_sync(0xffffffffu, sI, 16);
                float sH = f2sum(aN2[i]); sH += __shfl_xor_sync(0xffffffffu, sH, 16);
                float rg = sig_f(sR + cRf + dtv * wtRf);
                float zg = sig_f(sZ + cZf + dtv * wtZf);
                float ng = tanh_f(sI + biNf + dtv * wtNf + rg * (sH + bhNf));
                hn[i] = (1.0f - zg) * ng + zg * h_s[(r0A + i) * 132 + jF];
            }
            __syncthreads();
            if (ksA == 0) {
#pragma unroll
                for (int i = 0; i < 8; ++i)
                    h_s[(r0A + i) * 132 + jF] = hn[i];
            }
            __syncthreads();
#endif
        }

        // ===== sol_z[t] writer (coalesced 512B/warp) =====
        {
            float4 v = *reinterpret_cast<const float4 *>(&h_s[rW * 132 + cW]);
            *reinterpret_cast<float4 *>(
                &out_z[((size_t)(row0 + rW) * TT + t) * LL + cW]) = v;
        }

        // ===== Phase D: u = tanh(h @ w1^T + b1), tile 4x4, ksplit 4 =====
        {
            u64 c[16];
#pragma unroll
            for (int i = 0; i < 16; ++i) c[i] = 0;
            const char *wp = (const char *)(g_w1q + ksD * 128 + 4 * q4);
            const char *hp = (const char *)h_s + (size_t)(rqD * 4 * 132 + 4 * ksD) * 4;
#pragma unroll 2
            for (int kk = 0; kk < 8; ++kk) {
                ulonglong2 w0 = ld2g(wp);
                ulonglong2 w1r = ld2g(wp + 16);
                ulonglong2 w2r = ld2g(wp + 32);
                ulonglong2 w3r = ld2g(wp + 48);
#pragma unroll
                for (int i = 0; i < 4; ++i) {
                    ulonglong2 h = ld2s(hp + i * 528);
                    fma2(c[i * 4 + 0], w0.x,  h.x); fma2(c[i * 4 + 0], w0.y,  h.y);
                    fma2(c[i * 4 + 1], w1r.x, h.x); fma2(c[i * 4 + 1], w1r.y, h.y);
                    fma2(c[i * 4 + 2], w2r.x, h.x); fma2(c[i * 4 + 2], w2r.y, h.y);
                    fma2(c[i * 4 + 3], w3r.x, h.x); fma2(c[i * 4 + 3], w3r.y, h.y);
                }
                wp += 4 * 128 * 16;
                hp += 64;
            }
#pragma unroll
            for (int i = 0; i < 4; ++i) {
                float s0 = f2sum(c[i * 4 + 0]);
                float s1 = f2sum(c[i * 4 + 1]);
                float s2 = f2sum(c[i * 4 + 2]);
                float s3 = f2sum(c[i * 4 + 3]);
                s0 += __shfl_xor_sync(0xffffffffu, s0, 8);
                s1 += __shfl_xor_sync(0xffffffffu, s1, 8);
                s2 += __shfl_xor_sync(0xffffffffu, s2, 8);
                s3 += __shfl_xor_sync(0xffffffffu, s3, 8);
                s0 += __shfl_xor_sync(0xffffffffu, s0, 16);
                s1 += __shfl_xor_sync(0xffffffffu, s1, 16);
                s2 += __shfl_xor_sync(0xffffffffu, s2, 16);
                s3 += __shfl_xor_sync(0xffffffffu, s3, 16);
                if (ksD == 0) {
                    float4 uv = make_float4(tanh_f(s0 + b1v.x), tanh_f(s1 + b1v.y),
                                            tanh_f(s2 + b1v.z), tanh_f(s3 + b1v.w));
                    *reinterpret_cast<float4 *>(&u_s[(rqD * 4 + i) * 132 + 4 * q4]) = uv;
                }
            }
        }
        __syncthreads();

        // ===== Phase E: p = u @ w2^T + b2, tile 4x4, ksplit 8 =====
        {
            u64 c[16];
#pragma unroll
            for (int i = 0; i < 16; ++i) c[i] = 0;
            const char *wp = (const char *)(g_w2q + ksE * 64 + 4 * d4);
            const char *up = (const char *)u_s + (size_t)(rqE * 4 * 132 + 4 * ksE) * 4;
#pragma unroll
            for (int kk = 0; kk < 4; ++kk) {
                ulonglong2 w0 = ld2g(wp);
                ulonglong2 w1r = ld2g(wp + 16);
                ulonglong2 w2r = ld2g(wp + 32);
                ulonglong2 w3r = ld2g(wp + 48);
#pragma unroll
                for (int i = 0; i < 4; ++i) {
                    ulonglong2 u = ld2s(up + i * 528);
                    fma2(c[i * 4 + 0], w0.x,  u.x); fma2(c[i * 4 + 0], w0.y,  u.y);
                    fma2(c[i * 4 + 1], w1r.x, u.x); fma2(c[i * 4 + 1], w1r.y, u.y);
                    fma2(c[i * 4 + 2], w2r.x, u.x); fma2(c[i * 4 + 2], w2r.y, u.y);
                    fma2(c[i * 4 + 3], w3r.x, u.x); fma2(c[i * 4 + 3], w3r.y, u.y);
                }
                wp += 8 * 64 * 16;
                up += 128;
            }
#pragma unroll
            for (int i = 0; i < 4; ++i) {
                float s0 = f2sum(c[i * 4 + 0]);
                float s1 = f2sum(c[i * 4 + 1]);
                float s2 = f2sum(c[i * 4 + 2]);
                float s3 = f2sum(c[i * 4 + 3]);
                s0 += __shfl_xor_sync(0xffffffffu, s0, 4);
                s1 += __shfl_xor_sync(0xffffffffu, s1, 4);
                s2 += __shfl_xor_sync(0xffffffffu, s2, 4);
                s3 += __shfl_xor_sync(0xffffffffu, s3, 4);
                s0 += __shfl_xor_sync(0xffffffffu, s0, 8);
                s1 += __shfl_xor_sync(0xffffffffu, s1, 8);
                s2 += __shfl_xor_sync(0xffffffffu, s2, 8);
                s3 += __shfl_xor_sync(0xffffffffu, s3, 8);
                s0 += __shfl_xor_sync(0xffffffffu, s0, 16);
                s1 += __shfl_xor_sync(0xffffffffu, s1, 16);
                s2 += __shfl_xor_sync(0xffffffffu, s2, 16);
                s3 += __shfl_xor_sync(0xffffffffu, s3, 16);
                if (ksE == 0) {
                    float4 pv = make_float4(s0 + b2v.x, s1 + b2v.y,
                                            s2 + b2v.z, s3 + b2v.w);
                    int r = rqE * 4 + i;
                    *reinterpret_cast<float4 *>(&p_s[r * 68 + 4 * d4]) = pv;
                    *reinterpret_cast<float4 *>(
                        &out_p[((size_t)(row0 + r) * TT + t) * DD + 4 * d4]) = pv;
                }
            }
        }
        __syncthreads();       // p ready; next step's gates may start
    }

#if USE_TC
    __syncthreads();
    if (warp == 0) {
        TCDEALLOC(tmem_base, 64);
    }
#endif
}

// ---------------------------------------------------------------------------
// Launch
// ---------------------------------------------------------------------------
extern "C" void kernel_launch(void *const *d_in, const int *in_sizes, int n_in,
                              void *d_out, int out_size) {
    const float *fp   = (const float *)d_in[0];
    const float *ts   = (const float *)d_in[1];
    const float *w_ih = (const float *)d_in[2];
    const float *w_hh = (const float *)d_in[3];
    const float *b_ih = (const float *)d_in[4];
    const float *b_hh = (const float *)d_in[5];
    const float *w1   = (const float *)d_in[6];
    const float *b1   = (const float *)d_in[7];
    const float *w2   = (const float *)d_in[8];
    const float *b2   = (const float *)d_in[9];

    float *out_z = (float *)d_out;                       // sol_z  [1,B,T,L]
    float *out_p = out_z + (size_t)BB * TT * LL;         // pred_x [1,B,T,D]

    prep_kernel<<<64, 256>>>(w_ih, w1, w2);

    cudaFuncSetAttribute(rnn_kernel, cudaFuncAttributeMaxDynamicSharedMemorySize,
                         SM_TOTAL);
    rnn_kernel<<<NBLK, NTHR, SM_TOTAL>>>(fp, ts, w_hh, w_ih, b_ih, b_hh, b1, b2,
                                         out_z, out_p);
}

// round 17
// speedup vs baseline: 1.2741x; 1.0208x over previous
#include <cuda_runtime.h>
#include <cuda_bf16.h>
#include <math.h>
#include <stdint.h>

// Problem constants
#define BB 2048
#define TT 500
#define LL 128
#define DD 64
#define UU 128
#define RB 16              // batch rows per block
#define NBLK (BB / RB)     // 128 blocks
#define NTHR 512

// tcgen05 only exists in the arch-specific (sm_103a) device pass.
#if defined(__CUDA_ARCH_FEAT_SM103_ALL)
#define USE_TC 1
#else
#define USE_TC 0
#endif

typedef unsigned long long u64;

// ---------------------------------------------------------------------------
// f32x2 FMA helpers
// ---------------------------------------------------------------------------
__device__ __forceinline__ void fma2(u64 &c, u64 a, u64 b) {
    asm("fma.rn.f32x2 %0, %1, %2, %0;" : "+l"(c) : "l"(a), "l"(b));
}
__device__ __forceinline__ float f2sum(u64 v) {
    return __uint_as_float((unsigned)v) + __uint_as_float((unsigned)(v >> 32));
}
__device__ __forceinline__ ulonglong2 ld2s(const char *p) {            // LDS.128
    return *reinterpret_cast<const ulonglong2 *>(p);
}
__device__ __forceinline__ ulonglong2 ld2g(const char *p) {            // LDG.128
    return *reinterpret_cast<const ulonglong2 *>(p);
}
__device__ __forceinline__ float sig_f(float x) {
    return __fdividef(1.0f, 1.0f + __expf(-x));
}
__device__ __forceinline__ float tanh_f(float x) {
    return 2.0f * __fdividef(1.0f, 1.0f + __expf(-2.0f * x)) - 1.0f;
}

__device__ __forceinline__ uint32_t smem_u32(const void *p) {
    uint32_t a;
    asm("{ .reg .u64 t; cvta.to.shared.u64 t, %1; cvt.u32.u64 %0, t; }"
        : "=r"(a) : "l"(p));
    return a;
}

#if USE_TC
// ---------------------------------------------------------------------------
// tcgen05 / mbarrier PTX helpers (arch-specific pass only)
// ---------------------------------------------------------------------------
#define TCALLOC(sa, n)                                                        \
    asm volatile("tcgen05.alloc.cta_group::1.sync.aligned.shared::cta.b32 [%0], %1;" \
                 :: "r"(sa), "r"(n) : "memory")
#define TCDEALLOC(t, n)                                                       \
    asm volatile("tcgen05.dealloc.cta_group::1.sync.aligned.b32 %0, %1;"      \
                 :: "r"(t), "r"(n))
#define TCCOMMIT(m)                                                           \
    asm volatile("tcgen05.commit.cta_group::1.mbarrier::arrive::one.shared::cluster.b64 [%0];" \
                 :: "r"(m) : "memory")
#define TCFENCE_B() asm volatile("tcgen05.fence::before_thread_sync;" ::: "memory")
#define TCFENCE_A() asm volatile("tcgen05.fence::after_thread_sync;" ::: "memory")
#define TCWAIT_LD() asm volatile("tcgen05.wait::ld.sync.aligned;" ::: "memory")
#define FENCE_ASYNC() asm volatile("fence.proxy.async.shared::cta;" ::: "memory")
#define MBINIT(m, c)                                                          \
    asm volatile("mbarrier.init.shared.b64 [%0], %1;" :: "r"(m), "r"(c) : "memory")

#define MBWAIT(mbar_smem_addr, phase_parity) do {                             \
    uint32_t _mbar = (uint32_t)(mbar_smem_addr);                              \
    uint32_t _parity = (uint32_t)(phase_parity);                              \
    uint32_t _done;                                                           \
    asm volatile(                                                             \
        "{\n\t.reg .pred p;\n\t"                                              \
        "mbarrier.try_wait.parity.acquire.cta.shared::cta.b64 p, [%1], %2;\n\t" \
        "selp.b32 %0, 1, 0, p;\n\t}"                                          \
        : "=r"(_done) : "r"(_mbar), "r"(_parity) : "memory");                 \
    if (!_done) {                                                             \
        asm volatile(                                                         \
            "{\n\t.reg .pred P1;\n\t"                                         \
            "WAIT_LOOP_%=:\n\t"                                               \
            "mbarrier.try_wait.parity.acquire.cta.shared::cta.b64 P1, [%0], %1, 0x989680;\n\t" \
            "@P1 bra.uni WAIT_DONE_%=;\n\t"                                   \
            "bra.uni WAIT_LOOP_%=;\n\t"                                       \
            "WAIT_DONE_%=:\n\t}"                                              \
            :: "r"(_mbar), "r"(_parity) : "memory");                          \
    }                                                                         \
} while (0)

__device__ __forceinline__ void ldtm4(uint32_t *r, uint32_t ta) {
    asm volatile("tcgen05.ld.sync.aligned.32x32b.x4.b32 {%0,%1,%2,%3}, [%4];"
                 : "=r"(r[0]), "=r"(r[1]), "=r"(r[2]), "=r"(r[3]) : "r"(ta));
}

// idesc: dtype F32, atype BF16, btype BF16, N=16, M=128, K-major both
#define MMA_IDESC 0x8040490u

__device__ __forceinline__ void mma_ss(uint32_t d, uint64_t a, uint64_t b,
                                       uint32_t en) {
    asm volatile(
        "{\n\t.reg .pred p;\n\t"
        "setp.ne.u32 p, %4, 0;\n\t"
        "tcgen05.mma.cta_group::1.kind::f16 [%0], %1, %2, %3, {%5,%5,%5,%5}, p;\n\t}"
        :: "r"(d), "l"(a), "l"(b), "r"(MMA_IDESC), "r"(en), "r"(0u)
        : "memory");
}

// 64-bit SMEM descriptor (SW128, LBO=1, SBO=64)
#define DESC_BASE ((2ULL << 61) | (1ULL << 46) | (64ULL << 32) | (1ULL << 16))
__device__ __forceinline__ uint64_t mk_desc(uint32_t addr) {
    return DESC_BASE | ((uint64_t)(addr >> 4) & 0x3FFF);
}
#endif  // USE_TC

// Blocked-atom SW128 byte offsets (atom = 8 rows x 64 bf16 = 1024 B)
// A tile: 128 rows x 128 K (16 atom-rows, 2 atom-cols; col stride = 16 atoms)
__device__ __forceinline__ uint32_t a_off(int jj, int k) {
    uint32_t b = (uint32_t)((jj >> 3) + (k >> 6) * 16) * 1024u
               + (uint32_t)(jj & 7) * 128u + (uint32_t)(k & 63) * 2u;
    return b ^ ((b >> 3) & 0x70);
}
// B tile: 16 rows x 128 K (2 atom-rows, 2 atom-cols; col stride = 2 atoms)
__device__ __forceinline__ uint32_t b_off(int r, int k) {
    uint32_t b = (uint32_t)((r >> 3) + (k >> 6) * 2) * 1024u
               + (uint32_t)(r & 7) * 128u + (uint32_t)(k & 63) * 2u;
    return b ^ ((b >> 3) & 0x70);
}

// ---------------------------------------------------------------------------
// Streamed weights (prep kernel pre-pack)
// ---------------------------------------------------------------------------
__device__ float4 g_wihq[16 * 384];   // w_ih[:, 0:64]  : [k4<16][j<384]
__device__ float4 g_w1q [32 * 128];   // w1             : [k4<32][q<128]
__device__ float4 g_w2q [32 * 64];    // w2             : [q4<32][d<64]

__global__ void prep_kernel(const float *__restrict__ w_ih,
                            const float *__restrict__ w1,
                            const float *__restrict__ w2) {
    int idx = blockIdx.x * blockDim.x + threadIdx.x;
    int stride = gridDim.x * blockDim.x;
    for (int i = idx; i < 16 * 384; i += stride) {
        int k4 = i / 384, j = i % 384;
        const float *s = w_ih + j * 65 + 4 * k4;
        g_wihq[i] = make_float4(s[0], s[1], s[2], s[3]);
    }
    for (int i = idx; i < 32 * 128; i += stride) {
        int k4 = i / 128, q = i % 128;
        const float *s = w1 + q * 128 + 4 * k4;
        g_w1q[i] = make_float4(s[0], s[1], s[2], s[3]);
    }
    for (int i = idx; i < 32 * 64; i += stride) {
        int q4 = i / 64, d = i % 64;
        const float *s = w2 + d * 128 + 4 * q4;
        g_w2q[i] = make_float4(s[0], s[1], s[2], s[3]);
    }
}

// ---------------------------------------------------------------------------
// Shared memory layout (bytes) — identical footprint for BOTH paths.
// ---------------------------------------------------------------------------
#define SM_W0    0
#define SM_WHI   0                    // (tc) 3 gate tiles x 32768 bf16 hi
#define SM_WLO   98304                // (tc) bf16 lo
#define SM_HHI   196608               // (tc) h hi bf16 (4096)
#define SM_HLO   200704               // (tc) h lo bf16 (4096)
#define SM_H     204800               // h fp32 [16][132]  (8448)
#define SM_U     213248               // u fp32 [16][132]  (8448)
#define SM_P     221696               // p fp32 [16][68]   (4352)
#define SM_DT    226048               // dt [512]          (2048)
#define SM_MISC  228096               // [0]=tmem ptr, [8]=mbar
#define SM_TOTAL 228128               // <= 232448

__global__ void __launch_bounds__(NTHR, 1)
rnn_kernel(const float *__restrict__ fp,     // first_point [1,B,L]
           const float *__restrict__ ts,     // [T]
           const float *__restrict__ w_hh,   // [384,128]
           const float *__restrict__ w_ih,   // [384,65]
           const float *__restrict__ b_ih,   // [384]
           const float *__restrict__ b_hh,   // [384]
           const float *__restrict__ b1,     // [128]
           const float *__restrict__ b2,     // [64]
           float *__restrict__ out_z,        // [B,T,L]
           float *__restrict__ out_p)        // [B,T,D]
{
    extern __shared__ char sm[];
    float *h_s  = (float *)(sm + SM_H);
    float *u_s  = (float *)(sm + SM_U);
    float *p_s  = (float *)(sm + SM_P);
    float *dt_s = (float *)(sm + SM_DT);

    const int tid  = threadIdx.x;
    const int lane = tid & 31;
    const int warp = tid >> 5;
    const int row0 = blockIdx.x * RB;

#if USE_TC
    const uint32_t misc_sa = smem_u32(sm + SM_MISC);
    const uint32_t mbar_sa = misc_sa + 8;
    if (warp == 0) TCALLOC(misc_sa, 64);
    if (tid == 0)  MBINIT(mbar_sa, 3);       // 3 gate-issue warps commit

    // one-time: w_hh -> smem bf16 hi/lo in blocked-atom SW128 layout
    for (int i = tid; i < 384 * 128; i += NTHR) {
        int j = i >> 7, k = i & 127;
        float v = w_hh[j * 128 + k];
        __nv_bfloat16 hi = __float2bfloat16(v);
        float lo = v - __bfloat162float(hi);
        int g = j >> 7, jj = j & 127;
        uint32_t off = (uint32_t)g * 32768u + a_off(jj, k);
        *(__nv_bfloat16 *)(sm + SM_WHI + off) = hi;
        *(__nv_bfloat16 *)(sm + SM_WLO + off) = __float2bfloat16(lo);
    }
#else
    // one-time: w_hh -> smem fp32, whh4[k4*384 + j] = w_hh[j][4k4..4k4+3]
    float4 *whh4 = (float4 *)(sm + SM_W0);
    for (int i = tid; i < 32 * 384; i += NTHR) {
        int k4 = i / 384, j = i % 384;
        whh4[i] = *reinterpret_cast<const float4 *>(w_hh + j * 128 + 4 * k4);
    }
#endif
    for (int i = tid; i < TT; i += NTHR)
        dt_s[i] = (i == 0) ? 0.0f : (ts[i] - ts[i - 1]);

#if USE_TC
    // gates mapping (tc): thread -> (jA = TMEM lane, 4 rows rq*4..)
    const int jA = ((warp & 3) << 5) | lane;
    const int rq = warp >> 2;                   // 0..3
    const float cR  = b_ih[jA] + b_hh[jA];
    const float cZ  = b_ih[jA + 128] + b_hh[jA + 128];
    const float biN = b_ih[jA + 256];
    const float bhN = b_hh[jA + 256];
    const float wtR = w_ih[jA * 65 + 64];
    const float wtZ = w_ih[(jA + 128) * 65 + 64];
    const float wtN = w_ih[(jA + 256) * 65 + 64];
#else
    // gates mapping (fallback, R6): (jF 0..127, ksA lane bit4, 8-row half)
    const int jF  = ((warp & 7) << 4) | (lane & 15);
    const int ksA = lane >> 4;
    const int r0A = (warp >> 3) * 8;
    const float cRf  = b_ih[jF] + b_hh[jF];
    const float cZf  = b_ih[jF + 128] + b_hh[jF + 128];
    const float biNf = b_ih[jF + 256];
    const float bhNf = b_hh[jF + 256];
    const float wtRf = w_ih[jF * 65 + 64];
    const float wtZf = w_ih[(jF + 128) * 65 + 64];
    const float wtNf = w_ih[(jF + 256) * 65 + 64];
#endif

    // phase D mapping: (q4 in 0..31, rqD rows, ksD lane bits 3..4)
    const int q4  = ((warp & 3) << 3) | (lane & 7);
    const int ksD = lane >> 3;                 // 0..3
    const int rqD = warp >> 2;                 // 0..3
    const float4 b1v = *reinterpret_cast<const float4 *>(b1 + 4 * q4);

    // phase E mapping: (d4 in 0..15, rqE rows, ksE lane bits 2..4)
    const int d4  = ((warp & 3) << 2) | (lane & 3);
    const int ksE = lane >> 2;                 // 0..7
    const int rqE = warp >> 2;                 // 0..3
    const float4 b2v = *reinterpret_cast<const float4 *>(b2 + 4 * d4);

    // coalesced sol_z writer mapping
    const int rW = tid >> 5, cW = (tid & 31) * 4;

    // ---- load h0
    {
        float4 v = *reinterpret_cast<const float4 *>(fp + (size_t)(row0 + rW) * LL + cW);
        *reinterpret_cast<float4 *>(&h_s[rW * 132 + cW]) = v;
#if USE_TC
        float hv[4] = {v.x, v.y, v.z, v.w};
#pragma unroll
        for (int c = 0; c < 4; ++c) {
            __nv_bfloat16 hi = __float2bfloat16(hv[c]);
            float lo = hv[c] - __bfloat162float(hi);
            uint32_t off = b_off(rW, cW + c);
            *(__nv_bfloat16 *)(sm + SM_HHI + off) = hi;
            *(__nv_bfloat16 *)(sm + SM_HLO + off) = __float2bfloat16(lo);
        }
#endif
    }
#if USE_TC
    FENCE_ASYNC();
#endif
    __syncthreads();

#if USE_TC
    const uint32_t tmem_base = *(volatile uint32_t *)(sm + SM_MISC);
#endif

    for (int t = 0; t < TT; ++t) {
        if (t > 0) {
#if USE_TC
            // ===== issue gh MMAs (R14 placement; 3-warp split issue) =========
            // D[g] = w_hi*h_hi + w_hi*h_lo + w_lo*h_hi ; warps 0,1,2 issue one
            // gate tile each (disjoint TMEM D cols) and commit; mbar count 3.
            if (warp < 3 && lane == 0) {
                TCFENCE_A();   // pairs with readers' fence::before + barrier
                const int g = warp;
                uint64_t bHi = mk_desc(smem_u32(sm + SM_HHI));
                uint64_t bLo = mk_desc(smem_u32(sm + SM_HLO));
                uint32_t dcol = tmem_base + g * 16;
                uint64_t aHi = mk_desc(smem_u32(sm + SM_WHI + g * 32768));
                uint64_t aLo = mk_desc(smem_u32(sm + SM_WLO + g * 32768));
#pragma unroll
                for (int s = 0; s < 8; ++s) {
                    uint64_t ao = (uint64_t)((s & 3) * 2 + (s >> 2) * 1024);
                    uint64_t bo = (uint64_t)((s & 3) * 2 + (s >> 2) * 128);
                    mma_ss(dcol, aHi + ao, bHi + bo, (s == 0) ? 0u : 1u);
                }
#pragma unroll
                for (int s = 0; s < 8; ++s) {
                    uint64_t ao = (uint64_t)((s & 3) * 2 + (s >> 2) * 1024);
                    uint64_t bo = (uint64_t)((s & 3) * 2 + (s >> 2) * 128);
                    mma_ss(dcol, aHi + ao, bLo + bo, 1u);
                }
#pragma unroll
                for (int s = 0; s < 8; ++s) {
                    uint64_t ao = (uint64_t)((s & 3) * 2 + (s >> 2) * 1024);
                    uint64_t bo = (uint64_t)((s & 3) * 2 + (s >> 2) * 128);
                    mma_ss(dcol, aLo + ao, bHi + bo, 1u);
                }
                TCCOMMIT(mbar_sa);
            }

            // ===== gi = p @ w_ih[:, :64]^T in fp32 (overlaps MMA) ============
            u64 cRa[4], cZa[4], cNa[4];
#pragma unroll
            for (int i = 0; i < 4; ++i) { cRa[i] = 0; cZa[i] = 0; cNa[i] = 0; }
            {
                const char *wp = (const char *)(g_wihq + jA);
                const char *pp = (const char *)p_s + (size_t)(rq * 4) * 272;
#pragma unroll 4
                for (int k4 = 0; k4 < 16; ++k4) {
                    ulonglong2 wr = ld2g(wp);
                    ulonglong2 wz = ld2g(wp + 128 * 16);
                    ulonglong2 wn = ld2g(wp + 256 * 16);
#pragma unroll
                    for (int i = 0; i < 4; ++i) {
                        ulonglong2 p = ld2s(pp + i * 272);
                        fma2(cRa[i], wr.x, p.x); fma2(cRa[i], wr.y, p.y);
                        fma2(cZa[i], wz.x, p.x); fma2(cZa[i], wz.y, p.y);
                        fma2(cNa[i], wn.x, p.x); fma2(cNa[i], wn.y, p.y);
                    }
                    wp += 384 * 16;
                    pp += 16;
                }
            }

            // ===== wait MMA, read gh from TMEM, compute gates ================
            MBWAIT(mbar_sa, (uint32_t)((t - 1) & 1));
            TCFENCE_A();
            uint32_t gr[4], gz[4], gn[4];
            ldtm4(gr, tmem_base + 0 * 16 + 4 * rq);
            ldtm4(gz, tmem_base + 1 * 16 + 4 * rq);
            ldtm4(gn, tmem_base + 2 * 16 + 4 * rq);
            TCWAIT_LD();
            TCFENCE_B();

            const float dtv = dt_s[t];
#pragma unroll
            for (int i = 0; i < 4; ++i) {
                int r = 4 * rq + i;
                float rg = sig_f(f2sum(cRa[i]) + cR + dtv * wtR +
                                 __uint_as_float(gr[i]));
                float zg = sig_f(f2sum(cZa[i]) + cZ + dtv * wtZ +
                                 __uint_as_float(gz[i]));
                float ng = tanh_f(f2sum(cNa[i]) + biN + dtv * wtN +
                                  rg * (__uint_as_float(gn[i]) + bhN));
                float hold = h_s[r * 132 + jA];
                float hn = (1.0f - zg) * ng + zg * hold;
                h_s[r * 132 + jA] = hn;                 // same-thread rd/wr: safe
                __nv_bfloat16 hi = __float2bfloat16(hn);
                float lo = hn - __bfloat162float(hi);
                uint32_t off = b_off(r, jA);
                *(__nv_bfloat16 *)(sm + SM_HHI + off) = hi;
                *(__nv_bfloat16 *)(sm + SM_HLO + off) = __float2bfloat16(lo);
            }
            FENCE_ASYNC();
            __syncthreads();   // h_t (fp32 + bf16 split) visible block-wide
#else
            // ===== fallback (R6): fp32 gates, tile 8 rows x 3 gates, ksplit 2
            u64 aR[8], aZ[8], aN1[8], aN2[8];
#pragma unroll
            for (int i = 0; i < 8; ++i) { aR[i] = 0; aZ[i] = 0; aN1[i] = 0; aN2[i] = 0; }
            {
                const char *wp = (const char *)(whh4 + ksA * 384 + jF);
                const char *hp = (const char *)h_s + (size_t)(r0A * 132 + 4 * ksA) * 4;
#pragma unroll 4
                for (int kk = 0; kk < 16; ++kk) {
                    ulonglong2 wr = ld2s(wp);
                    ulonglong2 wz = ld2s(wp + 128 * 16);
                    ulonglong2 wn = ld2s(wp + 256 * 16);
#pragma unroll
                    for (int i = 0; i < 8; ++i) {
                        ulonglong2 h = ld2s(hp + i * 528);
                        fma2(aR[i],  wr.x, h.x); fma2(aR[i],  wr.y, h.y);
                        fma2(aZ[i],  wz.x, h.x); fma2(aZ[i],  wz.y, h.y);
                        fma2(aN2[i], wn.x, h.x); fma2(aN2[i], wn.y, h.y);
                    }
                    wp += 2 * 384 * 16;
                    hp += 32;
                }
            }
            {
                const char *wp = (const char *)(g_wihq + ksA * 384 + jF);
                const char *pp = (const char *)p_s + (size_t)(r0A * 68 + 4 * ksA) * 4;
#pragma unroll 2
                for (int kk = 0; kk < 8; ++kk) {
                    ulonglong2 wr = ld2g(wp);
                    ulonglong2 wz = ld2g(wp + 128 * 16);
                    ulonglong2 wn = ld2g(wp + 256 * 16);
#pragma unroll
                    for (int i = 0; i < 8; ++i) {
                        ulonglong2 p = ld2s(pp + i * 272);
                        fma2(aR[i],  wr.x, p.x); fma2(aR[i],  wr.y, p.y);
                        fma2(aZ[i],  wz.x, p.x); fma2(aZ[i],  wz.y, p.y);
                        fma2(aN1[i], wn.x, p.x); fma2(aN1[i], wn.y, p.y);
                    }
                    wp += 2 * 384 * 16;
                    pp += 32;
                }
            }
            const float dtv = dt_s[t];
            float hn[8];
#pragma unroll
            for (int i = 0; i < 8; ++i) {
                float sR = f2sum(aR[i]);  sR += __shfl_xor_sync(0xffffffffu, sR, 16);
                float sZ = f2sum(aZ[i]);  sZ += __shfl_xor_sync(0xffffffffu, sZ, 16);
                float sI = f2sum(aN1[i]); sI += __shfl_xor_sync(0xffffffffu, sI, 16);
                float sH = f2sum(aN2[i]); sH += __shfl_xor_sync(0xffffffffu, sH, 16);
                float rg = sig_f(sR + cRf + dtv * wtRf);
                float zg = sig_f(sZ + cZf + dtv * wtZf);
                float ng = tanh_f(sI + biNf + dtv * wtNf + rg * (sH + bhNf));
                hn[i] = (1.0f - zg) * ng + zg * h_s[(r0A + i) * 132 + jF];
            }
            __syncthreads();
            if (ksA == 0) {
#pragma unroll
                for (int i = 0; i < 8; ++i)
                    h_s[(r0A + i) * 132 + jF] = hn[i];
            }
            __syncthreads();
#endif
        }

        // ===== sol_z[t] writer (coalesced 512B/warp) =====
        {
            float4 v = *reinterpret_cast<const float4 *>(&h_s[rW * 132 + cW]);
            *reinterpret_cast<float4 *>(
                &out_z[((size_t)(row0 + rW) * TT + t) * LL + cW]) = v;
        }

        // ===== Phase D: u = tanh(h @ w1^T + b1), tile 4x4, ksplit 4 =====
        {
            u64 c[16];
#pragma unroll
            for (int i = 0; i < 16; ++i) c[i] = 0;
            const char *wp = (const char *)(g_w1q + ksD * 128 + 4 * q4);
            const char *hp = (const char *)h_s + (size_t)(rqD * 4 * 132 + 4 * ksD) * 4;
#pragma unroll 2
            for (int kk = 0; kk < 8; ++kk) {
                ulonglong2 w0 = ld2g(wp);
                ulonglong2 w1r = ld2g(wp + 16);
                ulonglong2 w2r = ld2g(wp + 32);
                ulonglong2 w3r = ld2g(wp + 48);
#pragma unroll
                for (int i = 0; i < 4; ++i) {
                    ulonglong2 h = ld2s(hp + i * 528);
                    fma2(c[i * 4 + 0], w0.x,  h.x); fma2(c[i * 4 + 0], w0.y,  h.y);
                    fma2(c[i * 4 + 1], w1r.x, h.x); fma2(c[i * 4 + 1], w1r.y, h.y);
                    fma2(c[i * 4 + 2], w2r.x, h.x); fma2(c[i * 4 + 2], w2r.y, h.y);
                    fma2(c[i * 4 + 3], w3r.x, h.x); fma2(c[i * 4 + 3], w3r.y, h.y);
                }
                wp += 4 * 128 * 16;
                hp += 64;
            }
#pragma unroll
            for (int i = 0; i < 4; ++i) {
                float s0 = f2sum(c[i * 4 + 0]);
                float s1 = f2sum(c[i * 4 + 1]);
                float s2 = f2sum(c[i * 4 + 2]);
                float s3 = f2sum(c[i * 4 + 3]);
                s0 += __shfl_xor_sync(0xffffffffu, s0, 8);
                s1 += __shfl_xor_sync(0xffffffffu, s1, 8);
                s2 += __shfl_xor_sync(0xffffffffu, s2, 8);
                s3 += __shfl_xor_sync(0xffffffffu, s3, 8);
                s0 += __shfl_xor_sync(0xffffffffu, s0, 16);
                s1 += __shfl_xor_sync(0xffffffffu, s1, 16);
                s2 += __shfl_xor_sync(0xffffffffu, s2, 16);
                s3 += __shfl_xor_sync(0xffffffffu, s3, 16);
                if (ksD == 0) {
                    float4 uv = make_float4(tanh_f(s0 + b1v.x), tanh_f(s1 + b1v.y),
                                            tanh_f(s2 + b1v.z), tanh_f(s3 + b1v.w));
                    *reinterpret_cast<float4 *>(&u_s[(rqD * 4 + i) * 132 + 4 * q4]) = uv;
                }
            }
        }
        __syncthreads();

        // ===== Phase E: p = u @ w2^T + b2, tile 4x4, ksplit 8 =====
        {
            u64 c[16];
#pragma unroll
            for (int i = 0; i < 16; ++i) c[i] = 0;
            const char *wp = (const char *)(g_w2q + ksE * 64 + 4 * d4);
            const char *up = (const char *)u_s + (size_t)(rqE * 4 * 132 + 4 * ksE) * 4;
#pragma unroll
            for (int kk = 0; kk < 4; ++kk) {
                ulonglong2 w0 = ld2g(wp);
                ulonglong2 w1r = ld2g(wp + 16);
                ulonglong2 w2r = ld2g(wp + 32);
                ulonglong2 w3r = ld2g(wp + 48);
#pragma unroll
                for (int i = 0; i < 4; ++i) {
                    ulonglong2 u = ld2s(up + i * 528);
                    fma2(c[i * 4 + 0], w0.x,  u.x); fma2(c[i * 4 + 0], w0.y,  u.y);
                    fma2(c[i * 4 + 1], w1r.x, u.x); fma2(c[i * 4 + 1], w1r.y, u.y);
                    fma2(c[i * 4 + 2], w2r.x, u.x); fma2(c[i * 4 + 2], w2r.y, u.y);
                    fma2(c[i * 4 + 3], w3r.x, u.x); fma2(c[i * 4 + 3], w3r.y, u.y);
                }
                wp += 8 * 64 * 16;
                up += 128;
            }
#pragma unroll
            for (int i = 0; i < 4; ++i) {
                float s0 = f2sum(c[i * 4 + 0]);
                float s1 = f2sum(c[i * 4 + 1]);
                float s2 = f2sum(c[i * 4 + 2]);
                float s3 = f2sum(c[i * 4 + 3]);
                s0 += __shfl_xor_sync(0xffffffffu, s0, 4);
                s1 += __shfl_xor_sync(0xffffffffu, s1, 4);
                s2 += __shfl_xor_sync(0xffffffffu, s2, 4);
                s3 += __shfl_xor_sync(0xffffffffu, s3, 4);
                s0 += __shfl_xor_sync(0xffffffffu, s0, 8);
                s1 += __shfl_xor_sync(0xffffffffu, s1, 8);
                s2 += __shfl_xor_sync(0xffffffffu, s2, 8);
                s3 += __shfl_xor_sync(0xffffffffu, s3, 8);
                s0 += __shfl_xor_sync(0xffffffffu, s0, 16);
                s1 += __shfl_xor_sync(0xffffffffu, s1, 16);
                s2 += __shfl_xor_sync(0xffffffffu, s2, 16);
                s3 += __shfl_xor_sync(0xffffffffu, s3, 16);
                if (ksE == 0) {
                    float4 pv = make_float4(s0 + b2v.x, s1 + b2v.y,
                                            s2 + b2v.z, s3 + b2v.w);
                    int r = rqE * 4 + i;
                    *reinterpret_cast<float4 *>(&p_s[r * 68 + 4 * d4]) = pv;
                    *reinterpret_cast<float4 *>(
                        &out_p[((size_t)(row0 + r) * TT + t) * DD + 4 * d4]) = pv;
                }
            }
        }
        __syncthreads();       // p ready; next step's gates may start
    }

#if USE_TC
    __syncthreads();
    if (warp == 0) {
        TCDEALLOC(tmem_base, 64);
    }
#endif
}

// ---------------------------------------------------------------------------
// Launch
// ---------------------------------------------------------------------------
extern "C" void kernel_launch(void *const *d_in, const int *in_sizes, int n_in,
                              void *d_out, int out_size) {
    const float *fp   = (const float *)d_in[0];
    const float *ts   = (const float *)d_in[1];
    const float *w_ih = (const float *)d_in[2];
    const float *w_hh = (const float *)d_in[3];
    const float *b_ih = (const float *)d_in[4];
    const float *b_hh = (const float *)d_in[5];
    const float *w1   = (const float *)d_in[6];
    const float *b1   = (const float *)d_in[7];
    const float *w2   = (const float *)d_in[8];
    const float *b2   = (const float *)d_in[9];

    float *out_z = (float *)d_out;                       // sol_z  [1,B,T,L]
    float *out_p = out_z + (size_t)BB * TT * LL;         // pred_x [1,B,T,D]

    prep_kernel<<<64, 256>>>(w_ih, w1, w2);

    cudaFuncSetAttribute(rnn_kernel, cudaFuncAttributeMaxDynamicSharedMemorySize,
                         SM_TOTAL);
    rnn_kernel<<<NBLK, NTHR, SM_TOTAL>>>(fp, ts, w_hh, w_ih, b_ih, b_hh, b1, b2,
                                         out_z, out_p);
}